// round 16
// baseline (speedup 1.0000x reference)
#include <cuda_runtime.h>
#include <cuda_fp16.h>
#include <math.h>
#include <float.h>
#include <stdint.h>

// Problem constants
#define NB 64
#define ND 256
#define NT 1024
#define NC 1024
#define NROWS (NB*NT)          // 65536
#define Q_SZ (NB*ND*NT)        // 16777216

// Output layout (flattened tuple, all float32)
#define LOSS_OFF Q_SZ
#define CMT_OFF  (Q_SZ+1)
#define IDX_OFF  (Q_SZ+2)
#define PERP_OFF (Q_SZ+2+NROWS)

// Single-term fp16 coarse score error sigma ~0.011; THETA ~ 13 sigma
// (proven exact in R11/R15). Flagged rows -> globally compacted list ->
// warp-per-row exact fp32 re-argmin (no block barriers).
#define THETA 0.15f

// Scratch (device globals; no allocations allowed)
__device__ float         g_enorm[NC];
__device__ int           g_idx[NROWS];
__device__ float         g_mindist[NROWS];
__device__ int           g_counts[NC];
__device__ __align__(16) unsigned g_Eh[NC*(ND/2)];  // fp16x2, [code][128 words]
__device__ int           g_ucnt;
__device__ int           g_unc[NROWS];

// ---------------- dynamic shared memory: vq_main (R11 layout) ---------------
#define SM_AH   0                          // X^T fp16x2: 128 rows x 132 words
#define SM_B    (SM_AH + 128*132*4)        // 67584: B chunk (6KB) / f32 stage
#define SM_EN   (SM_B + 16384)             // 83968: enorm 1024 f32
#define SM_XN   (SM_EN + 4096)             // 88064: xnorm partials 256 f32
#define SM_TOP  (SM_XN + 1024)             // 89088: 128 rows x 2 x 16B
#define SMEM_MAIN (SM_TOP + 4096)          // 93184 -> occupancy 2

// ------------------------------ helpers ------------------------------------
__device__ __forceinline__ unsigned h2u(__half2 h){
    return *reinterpret_cast<unsigned*>(&h);
}
__device__ __forceinline__ void mma16816h(float* c, const unsigned* a,
                                          const unsigned* b){
    asm volatile("mma.sync.aligned.m16n8k16.row.col.f32.f16.f16.f32 "
        "{%0,%1,%2,%3}, {%4,%5,%6,%7}, {%8,%9}, {%0,%1,%2,%3};"
        : "+f"(c[0]), "+f"(c[1]), "+f"(c[2]), "+f"(c[3])
        : "r"(a[0]), "r"(a[1]), "r"(a[2]), "r"(a[3]), "r"(b[0]), "r"(b[1]));
}
__device__ __forceinline__ unsigned ford(float f){
    unsigned u = __float_as_uint(f);
    return (u & 0x80000000u) ? ~u : (u | 0x80000000u);
}
__device__ __forceinline__ float fdec(unsigned u){
    return __uint_as_float((u & 0x80000000u) ? (u & 0x7FFFFFFFu) : ~u);
}

// ---------------------------------------------------------------------------
// K1a: per-code squared norms + zero histogram + zero uncertain counter
// ---------------------------------------------------------------------------
__global__ void prep_norm(const float* __restrict__ E){
    int j = blockIdx.x, lane = threadIdx.x;
    const float* er = E + (size_t)j * ND + lane * 8;
    float4 a = *(const float4*)er, b2 = *(const float4*)(er + 4);
    float s = a.x*a.x + a.y*a.y + a.z*a.z + a.w*a.w
            + b2.x*b2.x + b2.y*b2.y + b2.z*b2.z + b2.w*b2.w;
    #pragma unroll
    for (int o = 16; o; o >>= 1) s += __shfl_down_sync(0xffffffffu, s, o);
    if (lane == 0){
        g_enorm[j]  = s;
        g_counts[j] = 0;
        if (j == 0) g_ucnt = 0;
    }
}

// ---------------------------------------------------------------------------
// K1b: E -> packed fp16x2
// ---------------------------------------------------------------------------
__global__ void prep_cvt(const float* __restrict__ E){
    int id = blockIdx.x * 256 + threadIdx.x;      // word id, NC*128 total
    float2 v = *(const float2*)&E[(size_t)id * 2];
    g_Eh[id] = h2u(__floats2half2_rn(v.x, v.y));
}

// ---------------------------------------------------------------------------
// K2: coarse argmin via mma.sync m16n8k16 fp16 (single term), fp32 acc.
// (R11/R15 kernel, proven ~200-214us; epilogue emits compacted flagged list)
// ---------------------------------------------------------------------------
__global__ void __launch_bounds__(256,2) vq_main(const float* __restrict__ X){
    extern __shared__ char smem[];
    __shared__ int sNum, sBase;
    const int tid  = threadIdx.x;
    const int wid  = tid >> 5;
    const int lane = tid & 31;
    const int g    = lane >> 2;
    const int tig  = lane & 3;
    const int warpM = wid >> 1;
    const int warpN = wid & 1;
    const int b  = blockIdx.y;
    const int t0 = blockIdx.x * 128;

    unsigned* Ah = (unsigned*)(smem + SM_AH);
    unsigned* Bs = (unsigned*)(smem + SM_B);
    float* sEnorm = (float*)(smem + SM_EN);
    float* sXn    = (float*)(smem + SM_XN);
    float* sTop   = (float*)(smem + SM_TOP);

    for (int i = tid; i < NC; i += 256) sEnorm[i] = g_enorm[i];
    if (tid == 0) sNum = 0;

    // ---- phase 0: X [d][t] -> fp16 X^T [t][d] in smem, + exact xnorm ----
    {
        float* stage = (float*)(smem + SM_B);      // 32x128 f32 = 16KB
        const float* Xb = X + (size_t)b * ND * NT;
        const int t  = tid & 127;
        const int gg = tid >> 7;
        float xn = 0.f;
        for (int ch = 0; ch < 8; ch++){
            __syncthreads();
            for (int i = tid; i < 32*32; i += 256){
                int r = i >> 5, c4 = i & 31;
                float4 v = *(const float4*)&Xb[(size_t)(ch*32 + r)*NT + t0 + c4*4];
                *(float4*)&stage[r*128 + c4*4] = v;
            }
            __syncthreads();
            unsigned h2[8];
            #pragma unroll
            for (int p = 0; p < 8; p++){
                float v0 = stage[(gg*16 + 2*p    )*128 + t];
                float v1 = stage[(gg*16 + 2*p + 1)*128 + t];
                xn += v0*v0 + v1*v1;
                h2[p] = h2u(__floats2half2_rn(v0, v1));
            }
            int wbase = t*132 + ch*16 + gg*8;
            #pragma unroll
            for (int p = 0; p < 8; p++) Ah[wbase + p] = h2[p];
        }
        sXn[gg*128 + t] = xn;
        __syncthreads();
    }

    // ---- main loop: 128 chunks = 8 code-tiles x 16 k-chunks ----
    float acc[2][8][4];
    #pragma unroll
    for (int m = 0; m < 2; m++)
        #pragma unroll
        for (int n = 0; n < 8; n++)
            #pragma unroll
            for (int q = 0; q < 4; q++) acc[m][n][q] = 0.f;

    float rb1[4], rb2[4]; int ri[4];
    #pragma unroll
    for (int s = 0; s < 4; s++){ rb1[s] = -FLT_MAX; rb2[s] = -FLT_MAX; ri[s] = 0; }

    // register staging: 256 items of 16B (128 code-rows x 2), 1 per thread
    const int r0 = tid >> 1, p0 = tid & 1;
    const unsigned dstw0 = r0*12 + p0*4;
    uint4 stg0 = *(const uint4*)(g_Eh + r0*128 + p0*4);   // chunk 0

    for (int c = 0; c < 128; c++){
        const int kc = c & 15;
        const int jb = (c >> 4) * 128;

        __syncthreads();
        *(uint4*)&Bs[dstw0] = stg0;
        __syncthreads();

        if (c < 127){
            int cn = c + 1;
            int jb2 = (cn >> 4) * 128, kc2 = cn & 15;
            stg0 = *(const uint4*)(g_Eh + (jb2 + r0)*128 + kc2*8 + p0*4);
        }

        unsigned ah[2][4];
        #pragma unroll
        for (int m = 0; m < 2; m++){
            int row = warpM*32 + m*16 + g;
            int base = row*132 + kc*8 + tig;
            ah[m][0] = Ah[base];       ah[m][1] = Ah[base + 8*132];
            ah[m][2] = Ah[base + 4];   ah[m][3] = Ah[base + 8*132 + 4];
        }
        #pragma unroll
        for (int nt = 0; nt < 8; nt++){
            int nb = (warpN*64 + nt*8 + g)*12 + tig;
            unsigned bh[2] = { Bs[nb], Bs[nb + 4] };
            #pragma unroll
            for (int m = 0; m < 2; m++)
                mma16816h(acc[m][nt], ah[m], bh);
        }

        if (kc == 15){
            #pragma unroll
            for (int nt = 0; nt < 8; nt++){
                int cb = jb + warpN*64 + nt*8 + 2*tig;
                float en0 = sEnorm[cb], en1 = sEnorm[cb + 1];
                #pragma unroll
                for (int m = 0; m < 2; m++){
                    #pragma unroll
                    for (int h = 0; h < 2; h++){
                        int slot = m*2 + h;
                        float s0 = 2.f*acc[m][nt][h*2    ] - en0;
                        float s1 = 2.f*acc[m][nt][h*2 + 1] - en1;
                        if (s0 > rb1[slot]){ rb2[slot] = rb1[slot];
                                             rb1[slot] = s0; ri[slot] = cb; }
                        else if (s0 > rb2[slot]) rb2[slot] = s0;
                        if (s1 > rb1[slot]){ rb2[slot] = rb1[slot];
                                             rb1[slot] = s1; ri[slot] = cb + 1; }
                        else if (s1 > rb2[slot]) rb2[slot] = s1;
                    }
                }
            }
            #pragma unroll
            for (int m = 0; m < 2; m++)
                #pragma unroll
                for (int nt = 0; nt < 8; nt++)
                    #pragma unroll
                    for (int q = 0; q < 4; q++) acc[m][nt][q] = 0.f;
        }
    }

    // merge across tig lanes (disjoint code sets; tie -> lower index)
    #pragma unroll
    for (int s = 0; s < 4; s++){
        #pragma unroll
        for (int o = 1; o <= 2; o <<= 1){
            float ob1 = __shfl_xor_sync(0xffffffffu, rb1[s], o);
            float ob2 = __shfl_xor_sync(0xffffffffu, rb2[s], o);
            int   obi = __shfl_xor_sync(0xffffffffu, ri[s], o);
            if (ob1 > rb1[s] || (ob1 == rb1[s] && obi < ri[s])){
                rb2[s] = fmaxf(rb1[s], ob2);
                rb1[s] = ob1; ri[s] = obi;
            } else {
                rb2[s] = fmaxf(rb2[s], ob1);
            }
        }
    }
    if (tig == 0){
        #pragma unroll
        for (int s = 0; s < 4; s++){
            int row = warpM*32 + (s>>1)*16 + (s&1)*8 + g;
            float* tp = sTop + (row*2 + warpN)*4;
            tp[0] = rb1[s]; tp[1] = rb2[s];
            ((int*)tp)[2] = ri[s];
        }
    }
    __syncthreads();

    int myslot = -1, rowg = 0;
    if (tid < 128){
        const float* e0 = sTop + (tid*2    )*4;
        const float* e1 = sTop + (tid*2 + 1)*4;
        float b1 = e0[0], b2v = e0[1]; int bi = ((const int*)e0)[2];
        float o1 = e1[0], o2v = e1[1]; int oi = ((const int*)e1)[2];
        if (o1 > b1 || (o1 == b1 && oi < bi)){
            b2v = fmaxf(b1, o2v); b1 = o1; bi = oi;
        } else {
            b2v = fmaxf(b2v, o1);
        }
        float xnorm = sXn[tid] + sXn[128 + tid];
        rowg = b*NT + t0 + tid;
        g_idx[rowg]     = bi;
        g_mindist[rowg] = xnorm - b1;
        if (b1 - b2v < THETA) myslot = atomicAdd(&sNum, 1);
    }
    __syncthreads();
    if (tid == 0 && sNum > 0) sBase = atomicAdd(&g_ucnt, sNum);
    __syncthreads();
    if (myslot >= 0) g_unc[sBase + myslot] = rowg;
}

// ---------------------------------------------------------------------------
// K3: warp-per-row exact fp32 rescue, NO block barriers. 4096 warps grid-
// stride the flagged-row list. Per row: lane-partitioned x load into per-warp
// smem, shuffle xnorm, each lane rescores 32 codes (x broadcast LDS.128,
// E via L2 LDG.128, 4 accumulators), warp-max packed (score, ~idx).
// ---------------------------------------------------------------------------
__global__ void __launch_bounds__(256) vq_fix(const float* __restrict__ X,
                                              const float* __restrict__ E){
    __shared__ float4 sx4[8][65];     // per-warp x row (64 float4 + pad)
    const int wid  = threadIdx.x >> 5;
    const int lane = threadIdx.x & 31;
    const int gw   = blockIdx.x * 8 + wid;
    const int n    = g_ucnt;

    float* sxf = (float*)sx4[wid];

    for (int u = gw; u < n; u += 4096){
        int row = g_unc[u];
        int bb = row >> 10, tt = row & 1023;

        // lane loads dims lane*8 .. lane*8+7 (stride-NT gathers, MLP-covered)
        const float* xb = X + (size_t)bb * ND * NT + tt;
        float xs = 0.f;
        #pragma unroll
        for (int q = 0; q < 8; q++){
            float v = xb[(size_t)(lane*8 + q) * NT];
            sxf[lane*8 + q] = v;
            xs += v * v;
        }
        // warp xnorm reduce (fixed tree) + broadcast
        #pragma unroll
        for (int o = 16; o; o >>= 1) xs += __shfl_down_sync(0xffffffffu, xs, o);
        xs = __shfl_sync(0xffffffffu, xs, 0);
        __syncwarp();

        unsigned long long best = 0ull;
        for (int c = lane; c < NC; c += 32){
            const float4* er = (const float4*)(E + (size_t)c * ND);
            float d0 = 0.f, d1 = 0.f, d2 = 0.f, d3 = 0.f;
            #pragma unroll 16
            for (int q = 0; q < 64; q++){
                float4 ev = er[q];
                float4 xv = sx4[wid][q];     // broadcast
                d0 = fmaf(ev.x, xv.x, d0);
                d1 = fmaf(ev.y, xv.y, d1);
                d2 = fmaf(ev.z, xv.z, d2);
                d3 = fmaf(ev.w, xv.w, d3);
            }
            float sc = 2.f*((d0 + d1) + (d2 + d3)) - g_enorm[c];
            unsigned long long p =
                ((unsigned long long)ford(sc) << 32)
                | (unsigned)(0xFFFFFFFFu - (unsigned)c);
            if (p > best) best = p;          // tie -> lower idx via complement
        }
        #pragma unroll
        for (int o = 16; o; o >>= 1){
            unsigned long long ob = __shfl_down_sync(0xffffffffu, best, o);
            if (ob > best) best = ob;
        }
        if (lane == 0){
            int   idx = (int)(0xFFFFFFFFu - (unsigned)(best & 0xFFFFFFFFu));
            float sc  = fdec((unsigned)(best >> 32));
            g_idx[row]     = idx;
            g_mindist[row] = xs - sc;
        }
        __syncwarp();
    }
}

// ---------------------------------------------------------------------------
// K4: gather via smem transpose: coalesced E row reads, float4 stores.
// Also histogram + index output (reads FINAL g_idx).
// ---------------------------------------------------------------------------
__global__ void __launch_bounds__(256) vq_gather(const float* __restrict__ E,
                                                 float* __restrict__ out){
    __shared__ float sT[32][129];
    __shared__ int   sIdx[128];
    const int tid = threadIdx.x;
    const int wid = tid >> 5, lane = tid & 31;
    const int b  = blockIdx.y;
    const int t0 = blockIdx.x * 128;

    if (tid < 128){
        int row = b*NT + t0 + tid;
        int idx = g_idx[row];
        sIdx[tid] = idx;
        atomicAdd(&g_counts[idx], 1);
        out[IDX_OFF + row] = (float)idx;
    }
    float* ob = out + (size_t)b * ND * NT + t0;

    for (int dc = 0; dc < 8; dc++){
        __syncthreads();
        #pragma unroll
        for (int q = 0; q < 16; q++){
            int t = wid*16 + q;
            sT[lane][t] = E[(size_t)sIdx[t]*ND + dc*32 + lane];
        }
        __syncthreads();
        #pragma unroll
        for (int it = 0; it < 4; it++){
            int i = it*256 + tid;
            int dl = i >> 5, t4 = (i & 31)*4;
            float4 v = { sT[dl][t4], sT[dl][t4+1], sT[dl][t4+2], sT[dl][t4+3] };
            *(float4*)&ob[(size_t)(dc*32 + dl)*NT + t4] = v;
        }
    }
}

// ---------------------------------------------------------------------------
// K5: scalars (deterministic fixed-tree double reductions)
// ---------------------------------------------------------------------------
__global__ void vq_finalize(float* __restrict__ out){
    __shared__ double sh[1024];
    int tid = threadIdx.x;
    double loc = 0.0;
    for (int r = tid; r < NROWS; r += 1024) loc += (double)g_mindist[r];
    sh[tid] = loc; __syncthreads();
    for (int s = 512; s > 0; s >>= 1){
        if (tid < s) sh[tid] += sh[tid + s];
        __syncthreads();
    }
    double mse = sh[0] / (double)Q_SZ;
    __syncthreads();
    double p = (double)g_counts[tid] / (double)NROWS;
    sh[tid] = -p * log(p + 1e-10);
    __syncthreads();
    for (int s = 512; s > 0; s >>= 1){
        if (tid < s) sh[tid] += sh[tid + s];
        __syncthreads();
    }
    if (tid == 0){
        float m = (float)mse;
        out[LOSS_OFF] = m + 0.2f * m;
        out[CMT_OFF]  = m;
        out[PERP_OFF] = (float)exp(sh[0]);
    }
}

// ---------------------------------------------------------------------------
extern "C" void kernel_launch(void* const* d_in, const int* in_sizes, int n_in,
                              void* d_out, int out_size){
    const float* X = (const float*)d_in[0];  // [B, D, T] fp32
    const float* E = (const float*)d_in[1];  // [NC, D] fp32
    float* out = (float*)d_out;
    (void)in_sizes; (void)n_in; (void)out_size;

    cudaFuncSetAttribute(vq_main, cudaFuncAttributeMaxDynamicSharedMemorySize,
                         SMEM_MAIN);

    prep_norm  <<<NC, 32>>>(E);                          // 1
    prep_cvt   <<<NC*128/256, 256>>>(E);                 // 2
    vq_main    <<<dim3(8, NB), 256, SMEM_MAIN>>>(X);     // 3
    vq_fix     <<<512, 256>>>(X, E);                     // 4 <- profiled
    vq_gather  <<<dim3(8, NB), 256>>>(E, out);           // 5
    vq_finalize<<<1, 1024>>>(out);                       // 6
}

// round 17
// speedup vs baseline: 2.1972x; 2.1972x over previous
#include <cuda_runtime.h>
#include <cuda_fp16.h>
#include <math.h>
#include <float.h>
#include <stdint.h>

// Problem constants
#define NB 64
#define ND 256
#define NT 1024
#define NC 1024
#define NROWS (NB*NT)          // 65536
#define Q_SZ (NB*ND*NT)        // 16777216

// Output layout (flattened tuple, all float32)
#define LOSS_OFF Q_SZ
#define CMT_OFF  (Q_SZ+1)
#define IDX_OFF  (Q_SZ+2)
#define PERP_OFF (Q_SZ+2+NROWS)

// Single-term fp16 coarse score error sigma ~0.011; THETA ~ 13 sigma
// (proven exact in R11/R15). Flagged rows -> globally compacted list ->
// block-based exact fp32 re-argmin (E streamed once per 16-row group).
#define THETA 0.15f

// Scratch (device globals; no allocations allowed)
__device__ float         g_enorm[NC];
__device__ int           g_idx[NROWS];
__device__ float         g_mindist[NROWS];
__device__ int           g_counts[NC];
__device__ __align__(16) unsigned g_Eh[NC*(ND/2)];  // fp16x2, [code][128 words]
__device__ int           g_ucnt;
__device__ int           g_unc[NROWS];

// ---------------- dynamic shared memory: vq_main (R11 layout) ---------------
#define SM_AH   0                          // X^T fp16x2: 128 rows x 132 words
#define SM_B    (SM_AH + 128*132*4)        // 67584: B chunk (6KB) / f32 stage
#define SM_EN   (SM_B + 16384)             // 83968: enorm 1024 f32
#define SM_XN   (SM_EN + 4096)             // 88064: xnorm partials 256 f32
#define SM_TOP  (SM_XN + 1024)             // 89088: 128 rows x 2 x 16B
#define SMEM_MAIN (SM_TOP + 4096)          // 93184 -> occupancy 2

// ---------------- dynamic shared memory: vq_fix ----------------------------
#define FX_E    0                          // E tile [256 c][33 pad] f32
#define FX_X    (FX_E + 256*33*4)          // 33792: x rows [16][257]
#define FX_XN   (FX_X + 16*257*4)          // 50240: xnorm[16]
#define FX_BST  (FX_XN + 64)               // 50304: best u64 [16]
#define SMEM_FIX (FX_BST + 128)            // 50432

// ------------------------------ helpers ------------------------------------
__device__ __forceinline__ unsigned h2u(__half2 h){
    return *reinterpret_cast<unsigned*>(&h);
}
__device__ __forceinline__ void mma16816h(float* c, const unsigned* a,
                                          const unsigned* b){
    asm volatile("mma.sync.aligned.m16n8k16.row.col.f32.f16.f16.f32 "
        "{%0,%1,%2,%3}, {%4,%5,%6,%7}, {%8,%9}, {%0,%1,%2,%3};"
        : "+f"(c[0]), "+f"(c[1]), "+f"(c[2]), "+f"(c[3])
        : "r"(a[0]), "r"(a[1]), "r"(a[2]), "r"(a[3]), "r"(b[0]), "r"(b[1]));
}
__device__ __forceinline__ unsigned ford(float f){
    unsigned u = __float_as_uint(f);
    return (u & 0x80000000u) ? ~u : (u | 0x80000000u);
}
__device__ __forceinline__ float fdec(unsigned u){
    return __uint_as_float((u & 0x80000000u) ? (u & 0x7FFFFFFFu) : ~u);
}

// ---------------------------------------------------------------------------
// K1a: per-code squared norms + zero histogram + zero uncertain counter
// ---------------------------------------------------------------------------
__global__ void prep_norm(const float* __restrict__ E){
    int j = blockIdx.x, lane = threadIdx.x;
    const float* er = E + (size_t)j * ND + lane * 8;
    float4 a = *(const float4*)er, b2 = *(const float4*)(er + 4);
    float s = a.x*a.x + a.y*a.y + a.z*a.z + a.w*a.w
            + b2.x*b2.x + b2.y*b2.y + b2.z*b2.z + b2.w*b2.w;
    #pragma unroll
    for (int o = 16; o; o >>= 1) s += __shfl_down_sync(0xffffffffu, s, o);
    if (lane == 0){
        g_enorm[j]  = s;
        g_counts[j] = 0;
        if (j == 0) g_ucnt = 0;
    }
}

// ---------------------------------------------------------------------------
// K1b: E -> packed fp16x2
// ---------------------------------------------------------------------------
__global__ void prep_cvt(const float* __restrict__ E){
    int id = blockIdx.x * 256 + threadIdx.x;      // word id, NC*128 total
    float2 v = *(const float2*)&E[(size_t)id * 2];
    g_Eh[id] = h2u(__floats2half2_rn(v.x, v.y));
}

// ---------------------------------------------------------------------------
// K2: coarse argmin via mma.sync m16n8k16 fp16 (single term), fp32 acc.
// (R11/R15 kernel, proven ~200-214us; epilogue emits compacted flagged list)
// ---------------------------------------------------------------------------
__global__ void __launch_bounds__(256,2) vq_main(const float* __restrict__ X){
    extern __shared__ char smem[];
    __shared__ int sNum, sBase;
    const int tid  = threadIdx.x;
    const int wid  = tid >> 5;
    const int lane = tid & 31;
    const int g    = lane >> 2;
    const int tig  = lane & 3;
    const int warpM = wid >> 1;
    const int warpN = wid & 1;
    const int b  = blockIdx.y;
    const int t0 = blockIdx.x * 128;

    unsigned* Ah = (unsigned*)(smem + SM_AH);
    unsigned* Bs = (unsigned*)(smem + SM_B);
    float* sEnorm = (float*)(smem + SM_EN);
    float* sXn    = (float*)(smem + SM_XN);
    float* sTop   = (float*)(smem + SM_TOP);

    for (int i = tid; i < NC; i += 256) sEnorm[i] = g_enorm[i];
    if (tid == 0) sNum = 0;

    // ---- phase 0: X [d][t] -> fp16 X^T [t][d] in smem, + exact xnorm ----
    {
        float* stage = (float*)(smem + SM_B);      // 32x128 f32 = 16KB
        const float* Xb = X + (size_t)b * ND * NT;
        const int t  = tid & 127;
        const int gg = tid >> 7;
        float xn = 0.f;
        for (int ch = 0; ch < 8; ch++){
            __syncthreads();
            for (int i = tid; i < 32*32; i += 256){
                int r = i >> 5, c4 = i & 31;
                float4 v = *(const float4*)&Xb[(size_t)(ch*32 + r)*NT + t0 + c4*4];
                *(float4*)&stage[r*128 + c4*4] = v;
            }
            __syncthreads();
            unsigned h2[8];
            #pragma unroll
            for (int p = 0; p < 8; p++){
                float v0 = stage[(gg*16 + 2*p    )*128 + t];
                float v1 = stage[(gg*16 + 2*p + 1)*128 + t];
                xn += v0*v0 + v1*v1;
                h2[p] = h2u(__floats2half2_rn(v0, v1));
            }
            int wbase = t*132 + ch*16 + gg*8;
            #pragma unroll
            for (int p = 0; p < 8; p++) Ah[wbase + p] = h2[p];
        }
        sXn[gg*128 + t] = xn;
        __syncthreads();
    }

    // ---- main loop: 128 chunks = 8 code-tiles x 16 k-chunks ----
    float acc[2][8][4];
    #pragma unroll
    for (int m = 0; m < 2; m++)
        #pragma unroll
        for (int n = 0; n < 8; n++)
            #pragma unroll
            for (int q = 0; q < 4; q++) acc[m][n][q] = 0.f;

    float rb1[4], rb2[4]; int ri[4];
    #pragma unroll
    for (int s = 0; s < 4; s++){ rb1[s] = -FLT_MAX; rb2[s] = -FLT_MAX; ri[s] = 0; }

    // register staging: 256 items of 16B (128 code-rows x 2), 1 per thread
    const int r0 = tid >> 1, p0 = tid & 1;
    const unsigned dstw0 = r0*12 + p0*4;
    uint4 stg0 = *(const uint4*)(g_Eh + r0*128 + p0*4);   // chunk 0

    for (int c = 0; c < 128; c++){
        const int kc = c & 15;
        const int jb = (c >> 4) * 128;

        __syncthreads();
        *(uint4*)&Bs[dstw0] = stg0;
        __syncthreads();

        if (c < 127){
            int cn = c + 1;
            int jb2 = (cn >> 4) * 128, kc2 = cn & 15;
            stg0 = *(const uint4*)(g_Eh + (jb2 + r0)*128 + kc2*8 + p0*4);
        }

        unsigned ah[2][4];
        #pragma unroll
        for (int m = 0; m < 2; m++){
            int row = warpM*32 + m*16 + g;
            int base = row*132 + kc*8 + tig;
            ah[m][0] = Ah[base];       ah[m][1] = Ah[base + 8*132];
            ah[m][2] = Ah[base + 4];   ah[m][3] = Ah[base + 8*132 + 4];
        }
        #pragma unroll
        for (int nt = 0; nt < 8; nt++){
            int nb = (warpN*64 + nt*8 + g)*12 + tig;
            unsigned bh[2] = { Bs[nb], Bs[nb + 4] };
            #pragma unroll
            for (int m = 0; m < 2; m++)
                mma16816h(acc[m][nt], ah[m], bh);
        }

        if (kc == 15){
            #pragma unroll
            for (int nt = 0; nt < 8; nt++){
                int cb = jb + warpN*64 + nt*8 + 2*tig;
                float en0 = sEnorm[cb], en1 = sEnorm[cb + 1];
                #pragma unroll
                for (int m = 0; m < 2; m++){
                    #pragma unroll
                    for (int h = 0; h < 2; h++){
                        int slot = m*2 + h;
                        float s0 = 2.f*acc[m][nt][h*2    ] - en0;
                        float s1 = 2.f*acc[m][nt][h*2 + 1] - en1;
                        if (s0 > rb1[slot]){ rb2[slot] = rb1[slot];
                                             rb1[slot] = s0; ri[slot] = cb; }
                        else if (s0 > rb2[slot]) rb2[slot] = s0;
                        if (s1 > rb1[slot]){ rb2[slot] = rb1[slot];
                                             rb1[slot] = s1; ri[slot] = cb + 1; }
                        else if (s1 > rb2[slot]) rb2[slot] = s1;
                    }
                }
            }
            #pragma unroll
            for (int m = 0; m < 2; m++)
                #pragma unroll
                for (int nt = 0; nt < 8; nt++)
                    #pragma unroll
                    for (int q = 0; q < 4; q++) acc[m][nt][q] = 0.f;
        }
    }

    // merge across tig lanes (disjoint code sets; tie -> lower index)
    #pragma unroll
    for (int s = 0; s < 4; s++){
        #pragma unroll
        for (int o = 1; o <= 2; o <<= 1){
            float ob1 = __shfl_xor_sync(0xffffffffu, rb1[s], o);
            float ob2 = __shfl_xor_sync(0xffffffffu, rb2[s], o);
            int   obi = __shfl_xor_sync(0xffffffffu, ri[s], o);
            if (ob1 > rb1[s] || (ob1 == rb1[s] && obi < ri[s])){
                rb2[s] = fmaxf(rb1[s], ob2);
                rb1[s] = ob1; ri[s] = obi;
            } else {
                rb2[s] = fmaxf(rb2[s], ob1);
            }
        }
    }
    if (tig == 0){
        #pragma unroll
        for (int s = 0; s < 4; s++){
            int row = warpM*32 + (s>>1)*16 + (s&1)*8 + g;
            float* tp = sTop + (row*2 + warpN)*4;
            tp[0] = rb1[s]; tp[1] = rb2[s];
            ((int*)tp)[2] = ri[s];
        }
    }
    __syncthreads();

    int myslot = -1, rowg = 0;
    if (tid < 128){
        const float* e0 = sTop + (tid*2    )*4;
        const float* e1 = sTop + (tid*2 + 1)*4;
        float b1 = e0[0], b2v = e0[1]; int bi = ((const int*)e0)[2];
        float o1 = e1[0], o2v = e1[1]; int oi = ((const int*)e1)[2];
        if (o1 > b1 || (o1 == b1 && oi < bi)){
            b2v = fmaxf(b1, o2v); b1 = o1; bi = oi;
        } else {
            b2v = fmaxf(b2v, o1);
        }
        float xnorm = sXn[tid] + sXn[128 + tid];
        rowg = b*NT + t0 + tid;
        g_idx[rowg]     = bi;
        g_mindist[rowg] = xnorm - b1;
        if (b1 - b2v < THETA) myslot = atomicAdd(&sNum, 1);
    }
    __syncthreads();
    if (tid == 0 && sNum > 0) sBase = atomicAdd(&g_ucnt, sNum);
    __syncthreads();
    if (myslot >= 0) g_unc[sBase + myslot] = rowg;
}

// ---------------------------------------------------------------------------
// K3: block-based exact fp32 rescue, load-balanced via global list.
// v3: batched x-row load (all 16 rows in one MLP-covered phase, ONE barrier)
// + per-warp shuffle xnorms, then the proven R15 E-stream compute phase.
// ---------------------------------------------------------------------------
__global__ void __launch_bounds__(256,2) vq_fix(const float* __restrict__ X,
                                                const float* __restrict__ E){
    extern __shared__ char smem[];
    float* sE  = (float*)(smem + FX_E);               // [256][33]
    float* sx  = (float*)(smem + FX_X);               // [16][257]
    float* sxn = (float*)(smem + FX_XN);              // [16]
    unsigned long long* sB = (unsigned long long*)(smem + FX_BST);  // [16]

    const int tid = threadIdx.x;
    const int wid = tid >> 5, lane = tid & 31;
    const int bid = blockIdx.x;
    const int n = g_ucnt;

    for (int c0 = bid*16; c0 < n; c0 += 512*16){
        const int nf = min(16, n - c0);

        // batched x load: 16 rows x 256 dims, 16 outstanding loads/thread
        for (int i = tid; i < 16*256; i += 256){
            int r = i >> 8, d = i & 255;
            float v = 0.f;
            if (r < nf){
                int row = g_unc[c0 + r];
                v = X[(size_t)(row >> 10)*ND*NT + (size_t)d*NT + (row & 1023)];
            }
            sx[r*257 + d] = v;
        }
        if (tid < 16) sB[tid] = 0ull;
        __syncthreads();

        // xnorm: warp w handles rows w and w+8 (fixed order, deterministic)
        for (int r = wid; r < 16; r += 8){
            float s = 0.f;
            #pragma unroll
            for (int q = 0; q < 8; q++){
                float v = sx[r*257 + q*32 + lane];
                s += v*v;
            }
            #pragma unroll
            for (int o = 16; o; o >>= 1) s += __shfl_down_sync(0xffffffffu, s, o);
            if (lane == 0) sxn[r] = s;
        }
        __syncthreads();

        float acc[16];
        for (int ct = 0; ct < 4; ct++){           // code tiles of 256
            #pragma unroll
            for (int r = 0; r < 16; r++) acc[r] = 0.f;
            for (int kc = 0; kc < 8; kc++){       // k chunks of 32
                __syncthreads();
                for (int i = tid; i < 2048; i += 256){
                    int cc = i >> 3, k4 = i & 7;
                    float4 v = *(const float4*)&E[(size_t)(ct*256 + cc)*ND
                                                  + kc*32 + k4*4];
                    float* d = &sE[cc*33 + k4*4];
                    d[0] = v.x; d[1] = v.y; d[2] = v.z; d[3] = v.w;
                }
                __syncthreads();
                #pragma unroll 8
                for (int k = 0; k < 32; k++){
                    float ev = sE[tid*33 + k];
                    #pragma unroll
                    for (int r = 0; r < 16; r++){
                        if (r < nf)
                            acc[r] = fmaf(ev, sx[r*257 + kc*32 + k], acc[r]);
                    }
                }
            }
            int code = ct*256 + tid;
            float en = g_enorm[code];
            #pragma unroll
            for (int r = 0; r < 16; r++){
                if (r < nf){
                    float sc = 2.f*acc[r] - en;
                    unsigned long long p =
                        ((unsigned long long)ford(sc) << 32)
                        | (unsigned)(0xFFFFFFFFu - code);
                    atomicMax(&sB[r], p);
                }
            }
            __syncthreads();
        }

        if (tid < nf){
            unsigned long long p = sB[tid];
            int   idx = (int)(0xFFFFFFFFu - (unsigned)(p & 0xFFFFFFFFu));
            float sc  = fdec((unsigned)(p >> 32));
            int row = g_unc[c0 + tid];
            g_idx[row]     = idx;
            g_mindist[row] = sxn[tid] - sc;
        }
        __syncthreads();
    }
}

// ---------------------------------------------------------------------------
// K4: gather via smem transpose: coalesced E row reads, float4 stores.
// Also histogram + index output (reads FINAL g_idx).
// ---------------------------------------------------------------------------
__global__ void __launch_bounds__(256) vq_gather(const float* __restrict__ E,
                                                 float* __restrict__ out){
    __shared__ float sT[32][129];
    __shared__ int   sIdx[128];
    const int tid = threadIdx.x;
    const int wid = tid >> 5, lane = tid & 31;
    const int b  = blockIdx.y;
    const int t0 = blockIdx.x * 128;

    if (tid < 128){
        int row = b*NT + t0 + tid;
        int idx = g_idx[row];
        sIdx[tid] = idx;
        atomicAdd(&g_counts[idx], 1);
        out[IDX_OFF + row] = (float)idx;
    }
    float* ob = out + (size_t)b * ND * NT + t0;

    for (int dc = 0; dc < 8; dc++){
        __syncthreads();
        #pragma unroll
        for (int q = 0; q < 16; q++){
            int t = wid*16 + q;
            sT[lane][t] = E[(size_t)sIdx[t]*ND + dc*32 + lane];
        }
        __syncthreads();
        #pragma unroll
        for (int it = 0; it < 4; it++){
            int i = it*256 + tid;
            int dl = i >> 5, t4 = (i & 31)*4;
            float4 v = { sT[dl][t4], sT[dl][t4+1], sT[dl][t4+2], sT[dl][t4+3] };
            *(float4*)&ob[(size_t)(dc*32 + dl)*NT + t4] = v;
        }
    }
}

// ---------------------------------------------------------------------------
// K5: scalars (deterministic fixed-tree double reductions)
// ---------------------------------------------------------------------------
__global__ void vq_finalize(float* __restrict__ out){
    __shared__ double sh[1024];
    int tid = threadIdx.x;
    double loc = 0.0;
    for (int r = tid; r < NROWS; r += 1024) loc += (double)g_mindist[r];
    sh[tid] = loc; __syncthreads();
    for (int s = 512; s > 0; s >>= 1){
        if (tid < s) sh[tid] += sh[tid + s];
        __syncthreads();
    }
    double mse = sh[0] / (double)Q_SZ;
    __syncthreads();
    double p = (double)g_counts[tid] / (double)NROWS;
    sh[tid] = -p * log(p + 1e-10);
    __syncthreads();
    for (int s = 512; s > 0; s >>= 1){
        if (tid < s) sh[tid] += sh[tid + s];
        __syncthreads();
    }
    if (tid == 0){
        float m = (float)mse;
        out[LOSS_OFF] = m + 0.2f * m;
        out[CMT_OFF]  = m;
        out[PERP_OFF] = (float)exp(sh[0]);
    }
}

// ---------------------------------------------------------------------------
extern "C" void kernel_launch(void* const* d_in, const int* in_sizes, int n_in,
                              void* d_out, int out_size){
    const float* X = (const float*)d_in[0];  // [B, D, T] fp32
    const float* E = (const float*)d_in[1];  // [NC, D] fp32
    float* out = (float*)d_out;
    (void)in_sizes; (void)n_in; (void)out_size;

    cudaFuncSetAttribute(vq_main, cudaFuncAttributeMaxDynamicSharedMemorySize,
                         SMEM_MAIN);
    cudaFuncSetAttribute(vq_fix, cudaFuncAttributeMaxDynamicSharedMemorySize,
                         SMEM_FIX);

    prep_norm  <<<NC, 32>>>(E);                          // 1
    prep_cvt   <<<NC*128/256, 256>>>(E);                 // 2
    vq_main    <<<dim3(8, NB), 256, SMEM_MAIN>>>(X);     // 3
    vq_fix     <<<512, 256, SMEM_FIX>>>(X, E);           // 4 <- profiled
    vq_gather  <<<dim3(8, NB), 256>>>(E, out);           // 5
    vq_finalize<<<1, 1024>>>(out);                       // 6
}